// round 11
// baseline (speedup 1.0000x reference)
#include <cuda_runtime.h>
#include <cuda_bf16.h>
#include <mma.h>
#include <math.h>
#include <stdint.h>

using namespace nvcuda;

#define NJ 24
#define POSE_STRIDE (NJ * 3)
#define GROW 12
#define MAX_B 1024
#define MAX_ROWS (4 * MAX_B)      // 4 rows per batch (x=0..2 real, x=3 zero pad)
#define MAX_VPAD 8192
#define KSEC 128                  // padded K per split-section (97 real)
#define KTOT (3 * KSEC)           // 384: [Ah|Ah|Al] x [Bh|Bl|Bh]

__constant__ int c_par[NJ] = {-1, 0, 0, 0, 1, 2, 3, 4, 5, 6, 7, 8, 9, 9, 9,
                              12, 13, 14, 16, 17, 18, 19, 20, 21};

// scratch (no allocation)
__device__ float g_G[MAX_B * NJ * GROW];
__device__ __align__(256) __nv_bfloat16 g_A[(size_t)MAX_ROWS * KTOT];
__device__ __align__(256) __nv_bfloat16 g_Bm[(size_t)MAX_VPAD * KTOT];

// ---------------------------------------------------------------------------
// Kernel 1: forward kinematics (correctness-proven).
// ---------------------------------------------------------------------------
__global__ void fk_kernel(const float* __restrict__ pose,
                          const float* __restrict__ J_hat, int B) {
    int b = blockIdx.x;
    if (b >= B) return;
    __shared__ float Gs[NJ][GROW];
    int t = threadIdx.x;
    if (t < NJ) {
        float rx = pose[b * POSE_STRIDE + t * 3 + 0];
        float ry = pose[b * POSE_STRIDE + t * 3 + 1];
        float rz = pose[b * POSE_STRIDE + t * 3 + 2];
        float theta = sqrtf(rx * rx + ry * ry + rz * rz) + 1e-8f;
        float inv = 1.0f / theta;
        float ux = rx * inv, uy = ry * inv, uz = rz * inv;
        float c = cosf(theta), s = sinf(theta), ic = 1.0f - c;
        int p = c_par[t];
        float jx = J_hat[t * 3 + 0], jy = J_hat[t * 3 + 1], jz = J_hat[t * 3 + 2];
        if (p >= 0) { jx -= J_hat[p*3+0]; jy -= J_hat[p*3+1]; jz -= J_hat[p*3+2]; }
        Gs[t][0] = c + ic*ux*ux;  Gs[t][1] = ic*ux*uy - s*uz; Gs[t][2]  = ic*ux*uz + s*uy; Gs[t][3]  = jx;
        Gs[t][4] = ic*uy*ux+s*uz; Gs[t][5] = c + ic*uy*uy;    Gs[t][6]  = ic*uy*uz - s*ux; Gs[t][7]  = jy;
        Gs[t][8] = ic*uz*ux-s*uy; Gs[t][9] = ic*uz*uy + s*ux; Gs[t][10] = c + ic*uz*uz;    Gs[t][11] = jz;
    }
    __syncthreads();
    if (t == 0) {
        for (int i = 1; i < NJ; i++) {
            int p = c_par[i];
            float tmp[GROW];
            #pragma unroll
            for (int x = 0; x < 3; x++) {
                float p0 = Gs[p][x*4+0], p1 = Gs[p][x*4+1], p2 = Gs[p][x*4+2], p3 = Gs[p][x*4+3];
                tmp[x*4+0] = p0*Gs[i][0] + p1*Gs[i][4] + p2*Gs[i][8];
                tmp[x*4+1] = p0*Gs[i][1] + p1*Gs[i][5] + p2*Gs[i][9];
                tmp[x*4+2] = p0*Gs[i][2] + p1*Gs[i][6] + p2*Gs[i][10];
                tmp[x*4+3] = p0*Gs[i][3] + p1*Gs[i][7] + p2*Gs[i][11] + p3;
            }
            #pragma unroll
            for (int k = 0; k < GROW; k++) Gs[i][k] = tmp[k];
        }
    }
    __syncthreads();
    if (t < NJ) {
        float jx = J_hat[t*3+0], jy = J_hat[t*3+1], jz = J_hat[t*3+2];
        Gs[t][3]  -= Gs[t][0]*jx + Gs[t][1]*jy + Gs[t][2]*jz;
        Gs[t][7]  -= Gs[t][4]*jx + Gs[t][5]*jy + Gs[t][6]*jz;
        Gs[t][11] -= Gs[t][8]*jx + Gs[t][9]*jy + Gs[t][10]*jz;
    }
    __syncthreads();
    const float* src = &Gs[0][0];
    float* dst = g_G + (size_t)b * NJ * GROW;
    for (int i = t; i < NJ * GROW; i += blockDim.x) dst[i] = src[i];
}

// ---------------------------------------------------------------------------
// prep_A: one block per GEMM row (4b+x). K: [Ah | Ah | Al], 97 real cols.
// ---------------------------------------------------------------------------
__global__ void prep_A(const float* __restrict__ trans, int B) {
    int row = blockIdx.x;
    int k = threadIdx.x;                 // 0..127
    int b = row >> 2, x = row & 3;
    float val = 0.0f;
    if (b < B && x < 3) {
        if (k < 96) {
            int j = k >> 2, y = k & 3;
            val = g_G[(size_t)b * NJ * GROW + j * GROW + x * 4 + y];
        } else if (k == 96) {
            val = trans[b * 3 + x];
        }
    }
    __nv_bfloat16 hi = __float2bfloat16(val);
    __nv_bfloat16 lo = __float2bfloat16(val - __bfloat162float(hi));
    __nv_bfloat16* r = g_A + (size_t)row * KTOT;
    r[k] = hi; r[KSEC + k] = hi; r[2 * KSEC + k] = lo;
}

// ---------------------------------------------------------------------------
// prep_B: one block per padded vertex. m[4j+y] = w[v,j]*vh[v,y]; k=96 -> 1.
// K: [Bh | Bl | Bh].
// ---------------------------------------------------------------------------
__global__ void prep_B(const float* __restrict__ T_hat,
                       const float* __restrict__ W, int V) {
    int v = blockIdx.x;
    int k = threadIdx.x;                 // 0..127
    float val = 0.0f;
    if (v < V) {
        if (k < 96) {
            int j = k >> 2, y = k & 3;
            float vh = (y < 3) ? T_hat[v * 3 + y] : 1.0f;
            val = W[(size_t)v * NJ + j] * vh;
        } else if (k == 96) {
            val = 1.0f;
        }
    }
    __nv_bfloat16 hi = __float2bfloat16(val);
    __nv_bfloat16 lo = __float2bfloat16(val - __bfloat162float(hi));
    __nv_bfloat16* r = g_Bm + (size_t)v * KTOT;
    r[k] = hi; r[KSEC + k] = lo; r[2 * KSEC + k] = hi;
}

// ---------------------------------------------------------------------------
// GEMM via wmma bf16 (HMMA path, works on sm_100 base target).
// CTA: 256 thr = 8 warps in 4x2; warp tile 32x64; CTA tile 128 rows x 128 verts.
// Rows are 4-per-batch so a 128-row tile = exactly 32 batches.
// ---------------------------------------------------------------------------
#define LDC 68     // SMEM stage: 128 rows x (64 cols + 4 pad)

__global__ __launch_bounds__(256)
void gemm_kernel(float* __restrict__ out, int V, int B) {
    __shared__ float sm[128 * LDC];      // 34.8 KB

    int tid = threadIdx.x;
    int warp = tid >> 5;
    int wr = warp >> 1;                  // 0..3 row-warp
    int wc = warp & 1;                   // 0..1 col-warp
    int r0 = blockIdx.x * 128;
    int v0 = blockIdx.y * 128;

    wmma::fragment<wmma::accumulator, 16, 16, 16, float> acc[2][4];
    #pragma unroll
    for (int i = 0; i < 2; i++)
        #pragma unroll
        for (int j = 0; j < 4; j++)
            wmma::fill_fragment(acc[i][j], 0.0f);

    const __nv_bfloat16* Abase = g_A + (size_t)(r0 + wr * 32) * KTOT;
    const __nv_bfloat16* Bbase = g_Bm + (size_t)(v0 + wc * 64) * KTOT;

    #pragma unroll 4
    for (int k = 0; k < KTOT; k += 16) {
        wmma::fragment<wmma::matrix_a, 16, 16, 16, __nv_bfloat16, wmma::row_major> af[2];
        wmma::fragment<wmma::matrix_b, 16, 16, 16, __nv_bfloat16, wmma::col_major> bf[4];
        #pragma unroll
        for (int i = 0; i < 2; i++)
            wmma::load_matrix_sync(af[i], Abase + (size_t)i * 16 * KTOT + k, KTOT);
        #pragma unroll
        for (int j = 0; j < 4; j++)
            wmma::load_matrix_sync(bf[j], Bbase + (size_t)j * 16 * KTOT + k, KTOT);
        #pragma unroll
        for (int i = 0; i < 2; i++)
            #pragma unroll
            for (int j = 0; j < 4; j++)
                wmma::mma_sync(acc[i][j], af[i], bf[j], acc[i][j]);
    }

    // Epilogue: two passes (col-warp halves) through SMEM, coalesced float3 out.
    int b_base = r0 >> 2;
    for (int p = 0; p < 2; p++) {
        __syncthreads();
        if (wc == p) {
            #pragma unroll
            for (int i = 0; i < 2; i++)
                #pragma unroll
                for (int j = 0; j < 4; j++)
                    wmma::store_matrix_sync(sm + (wr * 32 + i * 16) * LDC + j * 16,
                                            acc[i][j], LDC, wmma::mem_row_major);
        }
        __syncthreads();

        // 32 batches x 64 verts in this half; 8 float3 per thread.
        #pragma unroll
        for (int idx = tid; idx < 32 * 64; idx += 256) {
            int bl = idx >> 6;
            int vl = idx & 63;
            int b = b_base + bl;
            int v = v0 + p * 64 + vl;
            if (b < B && v < V) {
                const float* srow = sm + (4 * bl) * LDC + vl;
                float* o = out + ((size_t)b * V + v) * 3;
                o[0] = srow[0 * LDC];
                o[1] = srow[1 * LDC];
                o[2] = srow[2 * LDC];
            }
        }
    }
}

// ---------------------------------------------------------------------------
// Launch: pure kernel launches only (graph-capture safe).
// ---------------------------------------------------------------------------
extern "C" void kernel_launch(void* const* d_in, const int* in_sizes, int n_in,
                              void* d_out, int out_size) {
    const float* T_hat   = (const float*)d_in[0];   // (V,3)
    const float* J_hat   = (const float*)d_in[1];   // (24,3)
    const float* weights = (const float*)d_in[2];   // (V,24)
    const float* pose    = (const float*)d_in[3];   // (B,72)
    const float* trans   = (const float*)d_in[4];   // (B,3)
    float* out = (float*)d_out;

    int V = in_sizes[0] / 3;
    int B = in_sizes[3] / POSE_STRIDE;
    if (B > MAX_B) B = MAX_B;

    int rows_pad = ((4 * B + 127) / 128) * 128;     // 2048 for B=512
    int vpad = ((V + 127) / 128) * 128;             // 6912 for V=6890
    if (rows_pad > MAX_ROWS) rows_pad = MAX_ROWS;
    if (vpad > MAX_VPAD) vpad = MAX_VPAD;

    fk_kernel<<<B, 32>>>(pose, J_hat, B);
    prep_A<<<rows_pad, 128>>>(trans, B);
    prep_B<<<vpad, 128>>>(T_hat, weights, V);

    dim3 grid(rows_pad / 128, vpad / 128);
    gemm_kernel<<<grid, 256>>>(out, V, B);
}

// round 12
// speedup vs baseline: 2.4817x; 2.4817x over previous
#include <cuda_runtime.h>
#include <cuda_bf16.h>
#include <mma.h>
#include <math.h>
#include <stdint.h>

using namespace nvcuda;

#define NJ 24
#define POSE_STRIDE (NJ * 3)
#define GROW 12
#define MAX_B 1024
#define MAX_ROWS (4 * MAX_B)      // 4 rows per batch (x=0..2 real, x=3 zero pad)
#define MAX_VPAD 8192
#define SEC 97                    // real K per split-section
#define KTOT 320                  // 3*97=291 padded to 320 (5 chunks of 64)
#define KC 64
#define NCHUNK (KTOT / KC)        // 5
#define LDS 72                    // SMEM leading dim (bf16 elems), 144B rows

__constant__ int c_par[NJ] = {-1, 0, 0, 0, 1, 2, 3, 4, 5, 6, 7, 8, 9, 9, 9,
                              12, 13, 14, 16, 17, 18, 19, 20, 21};

// scratch (no allocation)
__device__ float g_G[MAX_B * NJ * GROW];
__device__ __align__(256) __nv_bfloat16 g_A[(size_t)MAX_ROWS * KTOT];
__device__ __align__(256) __nv_bfloat16 g_Bm[(size_t)MAX_VPAD * KTOT];

__device__ __forceinline__ uint32_t smem_u32(const void* p) {
    uint32_t a;
    asm("{ .reg .u64 t; cvta.to.shared.u64 t, %1; cvt.u32.u64 %0, t; }"
        : "=r"(a) : "l"(p));
    return a;
}
__device__ __forceinline__ void cp_async16(uint32_t dst, const void* src) {
    asm volatile("cp.async.cg.shared.global [%0], [%1], 16;"
                 :: "r"(dst), "l"(src) : "memory");
}
__device__ __forceinline__ void cp_async_wait_all() {
    asm volatile("cp.async.commit_group;\n\tcp.async.wait_group 0;" ::: "memory");
}

// ---------------------------------------------------------------------------
// Kernel 1: forward kinematics (correctness-proven).
// ---------------------------------------------------------------------------
__global__ void fk_kernel(const float* __restrict__ pose,
                          const float* __restrict__ J_hat, int B) {
    int b = blockIdx.x;
    if (b >= B) return;
    __shared__ float Gs[NJ][GROW];
    int t = threadIdx.x;
    if (t < NJ) {
        float rx = pose[b * POSE_STRIDE + t * 3 + 0];
        float ry = pose[b * POSE_STRIDE + t * 3 + 1];
        float rz = pose[b * POSE_STRIDE + t * 3 + 2];
        float theta = sqrtf(rx * rx + ry * ry + rz * rz) + 1e-8f;
        float inv = 1.0f / theta;
        float ux = rx * inv, uy = ry * inv, uz = rz * inv;
        float c = cosf(theta), s = sinf(theta), ic = 1.0f - c;
        int p = c_par[t];
        float jx = J_hat[t * 3 + 0], jy = J_hat[t * 3 + 1], jz = J_hat[t * 3 + 2];
        if (p >= 0) { jx -= J_hat[p*3+0]; jy -= J_hat[p*3+1]; jz -= J_hat[p*3+2]; }
        Gs[t][0] = c + ic*ux*ux;  Gs[t][1] = ic*ux*uy - s*uz; Gs[t][2]  = ic*ux*uz + s*uy; Gs[t][3]  = jx;
        Gs[t][4] = ic*uy*ux+s*uz; Gs[t][5] = c + ic*uy*uy;    Gs[t][6]  = ic*uy*uz - s*ux; Gs[t][7]  = jy;
        Gs[t][8] = ic*uz*ux-s*uy; Gs[t][9] = ic*uz*uy + s*ux; Gs[t][10] = c + ic*uz*uz;    Gs[t][11] = jz;
    }
    __syncthreads();
    if (t == 0) {
        for (int i = 1; i < NJ; i++) {
            int p = c_par[i];
            float tmp[GROW];
            #pragma unroll
            for (int x = 0; x < 3; x++) {
                float p0 = Gs[p][x*4+0], p1 = Gs[p][x*4+1], p2 = Gs[p][x*4+2], p3 = Gs[p][x*4+3];
                tmp[x*4+0] = p0*Gs[i][0] + p1*Gs[i][4] + p2*Gs[i][8];
                tmp[x*4+1] = p0*Gs[i][1] + p1*Gs[i][5] + p2*Gs[i][9];
                tmp[x*4+2] = p0*Gs[i][2] + p1*Gs[i][6] + p2*Gs[i][10];
                tmp[x*4+3] = p0*Gs[i][3] + p1*Gs[i][7] + p2*Gs[i][11] + p3;
            }
            #pragma unroll
            for (int k = 0; k < GROW; k++) Gs[i][k] = tmp[k];
        }
    }
    __syncthreads();
    if (t < NJ) {
        float jx = J_hat[t*3+0], jy = J_hat[t*3+1], jz = J_hat[t*3+2];
        Gs[t][3]  -= Gs[t][0]*jx + Gs[t][1]*jy + Gs[t][2]*jz;
        Gs[t][7]  -= Gs[t][4]*jx + Gs[t][5]*jy + Gs[t][6]*jz;
        Gs[t][11] -= Gs[t][8]*jx + Gs[t][9]*jy + Gs[t][10]*jz;
    }
    __syncthreads();
    const float* src = &Gs[0][0];
    float* dst = g_G + (size_t)b * NJ * GROW;
    for (int i = t; i < NJ * GROW; i += blockDim.x) dst[i] = src[i];
}

// ---------------------------------------------------------------------------
// prep_A: one block per GEMM row (4b+x). K sections [Ah|Ah|Al] at 0/97/194,
// zeros at 291..319.
// ---------------------------------------------------------------------------
__global__ void prep_A(const float* __restrict__ trans, int B) {
    int row = blockIdx.x;
    int k = threadIdx.x;                 // 0..127
    int b = row >> 2, x = row & 3;
    __nv_bfloat16* r = g_A + (size_t)row * KTOT;
    if (k < SEC) {
        float val = 0.0f;
        if (b < B && x < 3) {
            if (k < 96) {
                int j = k >> 2, y = k & 3;
                val = g_G[(size_t)b * NJ * GROW + j * GROW + x * 4 + y];
            } else {
                val = trans[b * 3 + x];
            }
        }
        __nv_bfloat16 hi = __float2bfloat16(val);
        __nv_bfloat16 lo = __float2bfloat16(val - __bfloat162float(hi));
        r[k] = hi; r[SEC + k] = hi; r[2 * SEC + k] = lo;
    } else if (k < SEC + (KTOT - 3 * SEC)) {   // k = 97..125 -> 2*SEC+k = 291..319
        r[2 * SEC + k] = __float2bfloat16(0.0f);
    }
}

// ---------------------------------------------------------------------------
// prep_B: one block per padded vertex. Sections [Bh|Bl|Bh] at 0/97/194.
// m[4j+y] = w[v,j]*vh[v,y]; k=96 -> 1.
// ---------------------------------------------------------------------------
__global__ void prep_B(const float* __restrict__ T_hat,
                       const float* __restrict__ W, int V) {
    int v = blockIdx.x;
    int k = threadIdx.x;                 // 0..127
    __nv_bfloat16* r = g_Bm + (size_t)v * KTOT;
    if (k < SEC) {
        float val = 0.0f;
        if (v < V) {
            if (k < 96) {
                int j = k >> 2, y = k & 3;
                float vh = (y < 3) ? T_hat[v * 3 + y] : 1.0f;
                val = W[(size_t)v * NJ + j] * vh;
            } else {
                val = 1.0f;
            }
        }
        __nv_bfloat16 hi = __float2bfloat16(val);
        __nv_bfloat16 lo = __float2bfloat16(val - __bfloat162float(hi));
        r[k] = hi; r[SEC + k] = lo; r[2 * SEC + k] = hi;
    } else if (k < SEC + (KTOT - 3 * SEC)) {
        r[2 * SEC + k] = __float2bfloat16(0.0f);
    }
}

// ---------------------------------------------------------------------------
// GEMM via wmma bf16 with SMEM-staged K-chunks (cp.async + LDSM path).
// CTA: 256 thr = 8 warps (4 row x 2 col); warp tile 32x64; CTA tile 128x128.
// ---------------------------------------------------------------------------
#define LDC 68     // epilogue stage: 128 x (64 + 4 pad) floats

__global__ __launch_bounds__(256)
void gemm_kernel(float* __restrict__ out, int V, int B) {
    // union: GEMM stage (2 x 128x72 bf16 = 36.9 KB) / epilogue (128x68 f32 = 34.8 KB)
    __shared__ __align__(16) char smbuf[2 * 128 * LDS * 2];
    __nv_bfloat16* sA = reinterpret_cast<__nv_bfloat16*>(smbuf);
    __nv_bfloat16* sB = sA + 128 * LDS;
    float* sepi = reinterpret_cast<float*>(smbuf);

    int tid = threadIdx.x;
    int warp = tid >> 5;
    int wr = warp >> 1;                  // 0..3 row-warp
    int wc = warp & 1;                   // 0..1 col-warp
    int r0 = blockIdx.x * 128;
    int v0 = blockIdx.y * 128;

    wmma::fragment<wmma::accumulator, 16, 16, 16, float> acc[2][4];
    #pragma unroll
    for (int i = 0; i < 2; i++)
        #pragma unroll
        for (int j = 0; j < 4; j++)
            wmma::fill_fragment(acc[i][j], 0.0f);

    uint32_t sA32 = smem_u32(sA);
    uint32_t sB32 = smem_u32(sB);

    for (int c = 0; c < NCHUNK; c++) {
        // stage A/B chunk: 128 rows x 64 cols bf16 each, 16B per cp.async
        #pragma unroll
        for (int p = 0; p < 4; p++) {
            int idx = p * 256 + tid;             // 0..1023
            int row = idx >> 3, seg = idx & 7;
            uint32_t soff = (uint32_t)(row * LDS + seg * 8) * 2;
            const __nv_bfloat16* ga =
                g_A + (size_t)(r0 + row) * KTOT + c * KC + seg * 8;
            const __nv_bfloat16* gb =
                g_Bm + (size_t)(v0 + row) * KTOT + c * KC + seg * 8;
            cp_async16(sA32 + soff, ga);
            cp_async16(sB32 + soff, gb);
        }
        cp_async_wait_all();
        __syncthreads();

        #pragma unroll
        for (int ks = 0; ks < KC / 16; ks++) {
            int kk = ks * 16;
            wmma::fragment<wmma::matrix_a, 16, 16, 16, __nv_bfloat16, wmma::row_major> af[2];
            wmma::fragment<wmma::matrix_b, 16, 16, 16, __nv_bfloat16, wmma::col_major> bf[4];
            #pragma unroll
            for (int i = 0; i < 2; i++)
                wmma::load_matrix_sync(af[i], sA + (wr * 32 + i * 16) * LDS + kk, LDS);
            #pragma unroll
            for (int j = 0; j < 4; j++)
                wmma::load_matrix_sync(bf[j], sB + (wc * 64 + j * 16) * LDS + kk, LDS);
            #pragma unroll
            for (int i = 0; i < 2; i++)
                #pragma unroll
                for (int j = 0; j < 4; j++)
                    wmma::mma_sync(acc[i][j], af[i], bf[j], acc[i][j]);
        }
        __syncthreads();
    }

    // Epilogue: two passes (col-warp halves) through SMEM, coalesced float3 out.
    int b_base = r0 >> 2;
    for (int p = 0; p < 2; p++) {
        __syncthreads();
        if (wc == p) {
            #pragma unroll
            for (int i = 0; i < 2; i++)
                #pragma unroll
                for (int j = 0; j < 4; j++)
                    wmma::store_matrix_sync(sepi + (wr * 32 + i * 16) * LDC + j * 16,
                                            acc[i][j], LDC, wmma::mem_row_major);
        }
        __syncthreads();

        #pragma unroll
        for (int idx = tid; idx < 32 * 64; idx += 256) {
            int bl = idx >> 6;
            int vl = idx & 63;
            int b = b_base + bl;
            int v = v0 + p * 64 + vl;
            if (b < B && v < V) {
                const float* srow = sepi + (4 * bl) * LDC + vl;
                float* o = out + ((size_t)b * V + v) * 3;
                o[0] = srow[0 * LDC];
                o[1] = srow[1 * LDC];
                o[2] = srow[2 * LDC];
            }
        }
    }
}

// ---------------------------------------------------------------------------
// Launch: pure kernel launches only (graph-capture safe).
// ---------------------------------------------------------------------------
extern "C" void kernel_launch(void* const* d_in, const int* in_sizes, int n_in,
                              void* d_out, int out_size) {
    const float* T_hat   = (const float*)d_in[0];   // (V,3)
    const float* J_hat   = (const float*)d_in[1];   // (24,3)
    const float* weights = (const float*)d_in[2];   // (V,24)
    const float* pose    = (const float*)d_in[3];   // (B,72)
    const float* trans   = (const float*)d_in[4];   // (B,3)
    float* out = (float*)d_out;

    int V = in_sizes[0] / 3;
    int B = in_sizes[3] / POSE_STRIDE;
    if (B > MAX_B) B = MAX_B;

    int rows_pad = ((4 * B + 127) / 128) * 128;     // 2048 for B=512
    int vpad = ((V + 127) / 128) * 128;             // 6912 for V=6890
    if (rows_pad > MAX_ROWS) rows_pad = MAX_ROWS;
    if (vpad > MAX_VPAD) vpad = MAX_VPAD;

    fk_kernel<<<B, 32>>>(pose, J_hat, B);
    prep_A<<<rows_pad, 128>>>(trans, B);
    prep_B<<<vpad, 128>>>(T_hat, weights, V);

    dim3 grid(rows_pad / 128, vpad / 128);
    gemm_kernel<<<grid, 256>>>(out, V, B);
}